// round 8
// baseline (speedup 1.0000x reference)
#include <cuda_runtime.h>
#include <cuda_fp16.h>
#include <math.h>

#define N_NODES 100000
#define N_EDGES 1600000
#define FULL 0xffffffffu

// ---------------- scratch (static device globals; no allocations) ----------
// Edge record: {src | j<<20, dst, half2(b_j, b_j5), half2(b_j1, b_j6)}
__device__ int4   g_edge[N_EDGES];
__device__ float  g_deg[N_NODES];
__device__ float4 g_agg[N_NODES * 4];            // [N][16]; invariant: zero at call entry/exit
__device__ float4 g_h1[N_NODES * 4];             // hidden ping
__device__ float4 g_h2[N_NODES * 4];             // hidden pong
__device__ uint2  g_xwh[N_NODES * 100];          // [N][25][16] fp16 XW (80MB)

// ---------------- kernels --------------------------------------------------

__global__ void zero_deg_kernel() {
    int i = blockIdx.x * blockDim.x + threadIdx.x;
    if (i < N_NODES) g_deg[i] = 0.f;
}

__global__ void prep_kernel(const float2* __restrict__ attr,
                            const int* __restrict__ src,
                            const int* __restrict__ dst) {
    int e = blockIdx.x * blockDim.x + threadIdx.x;
    if (e >= N_EDGES) return;
    float2 a = attr[e];
    float v0 = a.x * 4.f, v1 = a.y * 4.f;
    float k0f = fminf(fmaxf(floorf(v0), 0.f), 3.f);
    float k1f = fminf(fmaxf(floorf(v1), 0.f), 3.f);
    float f0 = v0 - k0f, f1 = v1 - k1f;
    int k0 = (int)k0f, k1 = (int)k1f;
    float bj  = (1.f - f0) * (1.f - f1);
    float bj5 = (1.f - f0) * f1;
    float bj1 = f0 * (1.f - f1);
    float bj6 = f0 * f1;
    int j = k0 + 5 * k1;
    int d = dst[e];
    __half2 p0 = __floats2half2_rn(bj,  bj5);
    __half2 p1 = __floats2half2_rn(bj1, bj6);
    int4 rec;
    rec.x = src[e] | (j << 20);
    rec.y = d;
    rec.z = *reinterpret_cast<int*>(&p0);
    rec.w = *reinterpret_cast<int*>(&p1);
    g_edge[e] = rec;
    atomicAdd(&g_deg[d], 1.f);
}

__device__ __forceinline__ void red_add_v4(float* p, float4 v) {
    asm volatile("red.global.add.v4.f32 [%0], {%1,%2,%3,%4};"
                 :: "l"(p), "f"(v.x), "f"(v.y), "f"(v.z), "f"(v.w) : "memory");
}

__device__ __forceinline__ float2 h2f2(unsigned u) {
    __half2 h = *reinterpret_cast<__half2*>(&u);
    return __half22float2(h);
}

// Layer 1 edge kernel: in=2, 4 threads/edge, fp16 W1 in shared.
__global__ void edge1_kernel(const float2* __restrict__ x,
                             const float* __restrict__ W1) {
    __shared__ uint4 Wsh[100];                   // [25][4]
    if (threadIdx.x < 100) {
        int w = threadIdx.x >> 2, l = threadIdx.x & 3;
        const float4* Wv = (const float4*)W1;    // [25][2][4] float4
        float4 a0 = Wv[w * 8 + l];
        float4 a1 = Wv[w * 8 + 4 + l];
        __half2 p0 = __floats2half2_rn(a0.x, a0.y);
        __half2 p1 = __floats2half2_rn(a0.z, a0.w);
        __half2 p2 = __floats2half2_rn(a1.x, a1.y);
        __half2 p3 = __floats2half2_rn(a1.z, a1.w);
        uint4 u;
        u.x = *reinterpret_cast<unsigned*>(&p0);
        u.y = *reinterpret_cast<unsigned*>(&p1);
        u.z = *reinterpret_cast<unsigned*>(&p2);
        u.w = *reinterpret_cast<unsigned*>(&p3);
        Wsh[w * 4 + l] = u;
    }
    __syncthreads();
    int t = blockIdx.x * blockDim.x + threadIdx.x;   // E*4 threads exactly
    int e = t >> 2;
    int l = threadIdx.x & 3;
    int4 rec = g_edge[e];                        // quad-broadcast
    int s = rec.x & 0xFFFFF;
    int j = rec.x >> 20;
    float2 b0 = h2f2(rec.z);
    float2 b1 = h2f2(rec.w);
    float2 xv = x[s];
    const int woff[4] = {0, 5, 1, 6};
    float bs[4] = {b0.x, b0.y, b1.x, b1.y};
    float4 acc = make_float4(0.f, 0.f, 0.f, 0.f);
#pragma unroll
    for (int q = 0; q < 4; q++) {
        uint4 wv = Wsh[(j + woff[q]) * 4 + l];
        float2 w00 = h2f2(wv.x), w01 = h2f2(wv.y);
        float2 w10 = h2f2(wv.z), w11 = h2f2(wv.w);
        float c0 = bs[q] * xv.x, c1 = bs[q] * xv.y;
        acc.x += c0 * w00.x + c1 * w10.x;
        acc.y += c0 * w00.y + c1 * w10.y;
        acc.z += c0 * w01.x + c1 * w11.x;
        acc.w += c0 * w01.y + c1 * w11.y;
    }
    red_add_v4((float*)&g_agg[(size_t)rec.y * 4 + l], acc);
}

// Fused layer-1 node update + XW2 table build.
// Block = 128 threads, 100 nodes. Phase 1: h1 = relu(agg/deg + x@root + b)
// into shared + global (next layer root term), zero agg. Phase 2: standard
// xw build from shared with W2 register-resident per (k,o4) thread.
__global__ void node1_xw_kernel(const float2* __restrict__ x,
                                const float* __restrict__ root,
                                const float* __restrict__ bias,
                                const float* __restrict__ W2,
                                float4* __restrict__ hout) {
    __shared__ float4 hs[400];                   // 100 nodes x 16 floats
    __shared__ float4 rsh[8];
    __shared__ float4 bsh[4];
    int t = threadIdx.x;
    int n0 = blockIdx.x * 100;
    int k = t >> 2, o4 = t & 3;
    float4 wc[16];
    if (t < 100) {
        const float4* Wv = (const float4*)W2;    // [25][16][4]
#pragma unroll
        for (int i = 0; i < 16; i++) wc[i] = Wv[(k * 16 + i) * 4 + o4];
    }
    if (t < 8) rsh[t] = ((const float4*)root)[t];
    if (t < 4) bsh[t] = ((const float4*)bias)[t];
    __syncthreads();
    // phase 1: 400 (node, l) tasks
    for (int task = t; task < 400; task += 128) {
        int n = n0 + (task >> 2);
        int l = task & 3;
        float4 a = g_agg[(size_t)n * 4 + l];
        g_agg[(size_t)n * 4 + l] = make_float4(0.f, 0.f, 0.f, 0.f);
        float di = 1.f / fmaxf(g_deg[n], 1.f);
        float2 xv = x[n];
        float4 r0 = rsh[l], r1 = rsh[4 + l], bb = bsh[l];
        float4 o;
        o.x = fmaxf(bb.x + a.x * di + xv.x * r0.x + xv.y * r1.x, 0.f);
        o.y = fmaxf(bb.y + a.y * di + xv.x * r0.y + xv.y * r1.y, 0.f);
        o.z = fmaxf(bb.z + a.z * di + xv.x * r0.z + xv.y * r1.z, 0.f);
        o.w = fmaxf(bb.w + a.w * di + xv.x * r0.w + xv.y * r1.w, 0.f);
        hs[task] = o;
        hout[(size_t)n * 4 + l] = o;
    }
    __syncthreads();
    // phase 2: xw build
    if (t >= 100) return;
    const float* hsf = (const float*)hs;
    for (int n = 0; n < 100; n++) {
        float4 a = make_float4(0.f, 0.f, 0.f, 0.f);
#pragma unroll
        for (int i = 0; i < 16; i++) {
            float hv = hsf[n * 16 + i];
            a.x += hv * wc[i].x; a.y += hv * wc[i].y;
            a.z += hv * wc[i].z; a.w += hv * wc[i].w;
        }
        __half2 h0 = __floats2half2_rn(a.x, a.y);
        __half2 h1 = __floats2half2_rn(a.z, a.w);
        uint2 u;
        u.x = *reinterpret_cast<unsigned*>(&h0);
        u.y = *reinterpret_cast<unsigned*>(&h1);
        g_xwh[((size_t)(n0 + n) * 25 + k) * 4 + o4] = u;
    }
}

// Fused layer-2 node update + XW3 table build (16-channel root).
__global__ void node16_xw_kernel(const float4* __restrict__ hin,
                                 const float* __restrict__ root,
                                 const float* __restrict__ bias,
                                 const float* __restrict__ W3,
                                 float4* __restrict__ hout) {
    __shared__ float4 hsin[400];                 // prev h block
    __shared__ float4 hs[400];                   // new h block
    __shared__ float4 rsh[64];
    __shared__ float4 bsh[4];
    int t = threadIdx.x;
    int n0 = blockIdx.x * 100;
    int k = t >> 2, o4 = t & 3;
    float4 wc[16];
    if (t < 100) {
        const float4* Wv = (const float4*)W3;    // [25][16][4]
#pragma unroll
        for (int i = 0; i < 16; i++) wc[i] = Wv[(k * 16 + i) * 4 + o4];
    }
    if (t < 64) rsh[t] = ((const float4*)root)[t];
    if (t < 4)  bsh[t] = ((const float4*)bias)[t];
    for (int j = t; j < 400; j += 128) hsin[j] = hin[(size_t)n0 * 4 + j];
    __syncthreads();
    // phase 1: 400 (node, l) tasks
    const float* hinf = (const float*)hsin;
    for (int task = t; task < 400; task += 128) {
        int nn = task >> 2;                      // local node
        int n = n0 + nn;
        int l = task & 3;
        float4 a = g_agg[(size_t)n * 4 + l];
        g_agg[(size_t)n * 4 + l] = make_float4(0.f, 0.f, 0.f, 0.f);
        float di = 1.f / fmaxf(g_deg[n], 1.f);
        float4 acc = bsh[l];
        acc.x += a.x * di; acc.y += a.y * di; acc.z += a.z * di; acc.w += a.w * di;
#pragma unroll
        for (int i = 0; i < 16; i++) {
            float hv = hinf[nn * 16 + i];
            float4 r = rsh[i * 4 + l];
            acc.x += hv * r.x; acc.y += hv * r.y; acc.z += hv * r.z; acc.w += hv * r.w;
        }
        acc.x = fmaxf(acc.x, 0.f); acc.y = fmaxf(acc.y, 0.f);
        acc.z = fmaxf(acc.z, 0.f); acc.w = fmaxf(acc.w, 0.f);
        hs[task] = acc;
        hout[(size_t)n * 4 + l] = acc;
    }
    __syncthreads();
    // phase 2: xw build
    if (t >= 100) return;
    const float* hsf = (const float*)hs;
    for (int n = 0; n < 100; n++) {
        float4 a = make_float4(0.f, 0.f, 0.f, 0.f);
#pragma unroll
        for (int i = 0; i < 16; i++) {
            float hv = hsf[n * 16 + i];
            a.x += hv * wc[i].x; a.y += hv * wc[i].y;
            a.z += hv * wc[i].z; a.w += hv * wc[i].w;
        }
        __half2 h0 = __floats2half2_rn(a.x, a.y);
        __half2 h1 = __floats2half2_rn(a.z, a.w);
        uint2 u;
        u.x = *reinterpret_cast<unsigned*>(&h0);
        u.y = *reinterpret_cast<unsigned*>(&h1);
        g_xwh[((size_t)(n0 + n) * 25 + k) * 4 + o4] = u;
    }
}

// Edge gather for layers 2/3: 4 threads/edge; adjacent tap pairs as 64B
// quad loads, shfl_xor(2) recombine, lane-permuted single 64B atomic quad.
__global__ void edge_gather_kernel() {
    int t = blockIdx.x * blockDim.x + threadIdx.x;
    int e = t >> 2;
    int l = threadIdx.x & 3;
    int4 rec = g_edge[e];
    int s = rec.x & 0xFFFFF;
    int j = rec.x >> 20;
    float2 b0 = h2f2(rec.z);
    float2 b1 = h2f2(rec.w);
    const char* base = (const char*)g_xwh + (size_t)s * 800 + l * 16;
    uint4 v1 = *reinterpret_cast<const uint4*>(base + j * 32);
    uint4 v2 = *reinterpret_cast<const uint4*>(base + (j + 5) * 32);
    float cA = (l & 2) ? b1.x : b0.x;
    float cB = (l & 2) ? b1.y : b0.y;
    float acc[8];
    const unsigned* u1 = reinterpret_cast<const unsigned*>(&v1);
    const unsigned* u2 = reinterpret_cast<const unsigned*>(&v2);
#pragma unroll
    for (int i = 0; i < 4; i++) {
        float2 f1 = h2f2(u1[i]);
        float2 f2 = h2f2(u2[i]);
        acc[2 * i]     = cA * f1.x + cB * f2.x;
        acc[2 * i + 1] = cA * f1.y + cB * f2.y;
    }
#pragma unroll
    for (int i = 0; i < 8; i++)
        acc[i] += __shfl_xor_sync(FULL, acc[i], 2);
    float* ap = (float*)g_agg + (size_t)rec.y * 16 + ((l & 1) << 3) + ((l & 2) << 1);
    float4 out = (l & 2) ? make_float4(acc[4], acc[5], acc[6], acc[7])
                         : make_float4(acc[0], acc[1], acc[2], acc[3]);
    red_add_v4(ap, out);
}

// Layer-3 node update fused with fc head: relu(...) -> dot fc_w -> sigmoid.
__global__ void node16_final_kernel(const float4* __restrict__ hin,
                                    const float* __restrict__ root,
                                    const float* __restrict__ bias,
                                    const float* __restrict__ fcw,
                                    const float* __restrict__ fcb,
                                    float* __restrict__ out) {
    __shared__ float4 rsh[64];
    __shared__ float4 bsh[4];
    __shared__ float4 wsh[4];
    for (int j = threadIdx.x; j < 64; j += blockDim.x)
        rsh[j] = ((const float4*)root)[j];
    if (threadIdx.x < 4) {
        bsh[threadIdx.x] = ((const float4*)bias)[threadIdx.x];
        wsh[threadIdx.x] = ((const float4*)fcw)[threadIdx.x];
    }
    __syncthreads();
    int t = blockIdx.x * blockDim.x + threadIdx.x;
    int n = t >> 2;
    if (n >= N_NODES) return;
    int l = t & 3;
    float4 a = g_agg[(size_t)n * 4 + l];
    float di = 1.f / fmaxf(g_deg[n], 1.f);
    float4 acc = bsh[l];
    acc.x += a.x * di; acc.y += a.y * di; acc.z += a.z * di; acc.w += a.w * di;
    const float* h = (const float*)(hin + (size_t)n * 4);
#pragma unroll
    for (int i = 0; i < 16; i++) {
        float hv = h[i];
        float4 r = rsh[i * 4 + l];
        acc.x += hv * r.x; acc.y += hv * r.y; acc.z += hv * r.z; acc.w += hv * r.w;
    }
    acc.x = fmaxf(acc.x, 0.f); acc.y = fmaxf(acc.y, 0.f);
    acc.z = fmaxf(acc.z, 0.f); acc.w = fmaxf(acc.w, 0.f);
    g_agg[(size_t)n * 4 + l] = make_float4(0.f, 0.f, 0.f, 0.f);
    float4 wv = wsh[l];
    float z = acc.x * wv.x + acc.y * wv.y + acc.z * wv.z + acc.w * wv.w;
    z += __shfl_xor_sync(FULL, z, 1);
    z += __shfl_xor_sync(FULL, z, 2);
    if (l == 0) out[n] = 1.f / (1.f + expf(-(z + fcb[0])));
}

// ---------------- launch ---------------------------------------------------

extern "C" void kernel_launch(void* const* d_in, const int* in_sizes, int n_in,
                              void* d_out, int out_size) {
    const float2* x     = (const float2*)d_in[0];
    const int*    ei    = (const int*)d_in[1];
    const float2* attr  = (const float2*)d_in[2];
    const float*  W1    = (const float*)d_in[3];
    const float*  root1 = (const float*)d_in[4];
    const float*  b1    = (const float*)d_in[5];
    const float*  W2    = (const float*)d_in[6];
    const float*  root2 = (const float*)d_in[7];
    const float*  b2    = (const float*)d_in[8];
    const float*  W3    = (const float*)d_in[9];
    const float*  root3 = (const float*)d_in[10];
    const float*  b3    = (const float*)d_in[11];
    const float*  fcw   = (const float*)d_in[12];
    const float*  fcb   = (const float*)d_in[13];
    const int* src = ei;
    const int* dst = ei + N_EDGES;

    float4 *h1, *h2;
    cudaGetSymbolAddress((void**)&h1, g_h1);
    cudaGetSymbolAddress((void**)&h2, g_h2);

    const int TB = 256;
    int gEdge  = (N_EDGES + TB - 1) / TB;
    int gEdge4 = (N_EDGES * 4) / TB;             // exact: 25000
    int gNode4 = (N_NODES * 4 + TB - 1) / TB;
    int gNode  = (N_NODES + TB - 1) / TB;

    zero_deg_kernel<<<gNode, TB>>>();
    prep_kernel<<<gEdge, TB>>>(attr, src, dst);

    // layer 1 edge phase
    edge1_kernel<<<gEdge4, TB>>>(x, W1);
    // fused: layer-1 node update + XW2 build
    node1_xw_kernel<<<N_NODES / 100, 128>>>(x, root1, b1, W2, h1);

    // layer 2 edge phase
    edge_gather_kernel<<<gEdge4, TB>>>();
    // fused: layer-2 node update + XW3 build
    node16_xw_kernel<<<N_NODES / 100, 128>>>(h1, root2, b2, W3, h2);

    // layer 3 edge phase + fused node update / fc head
    edge_gather_kernel<<<gEdge4, TB>>>();
    node16_final_kernel<<<gNode4, TB>>>(h2, root3, b3, fcw, fcb, (float*)d_out);
}

// round 9
// speedup vs baseline: 1.1780x; 1.1780x over previous
#include <cuda_runtime.h>
#include <cuda_fp16.h>
#include <math.h>

#define N_NODES 100000
#define N_EDGES 1600000
#define HALF_E  (N_EDGES / 2)
#define FULL 0xffffffffu

// ---------------- scratch (static device globals; no allocations) ----------
// Edge record: {src | j<<20, dst, half2(b_j, b_j5), half2(b_j1, b_j6)}
__device__ int4   g_edge[N_EDGES];
__device__ float  g_deg[N_NODES];
__device__ float4 g_agg[N_NODES * 4];            // [N][16]; zero at call entry/exit
__device__ float4 g_h1[N_NODES * 4];             // hidden ping
__device__ float4 g_h2[N_NODES * 4];             // hidden pong
__device__ uint2  g_xwh[N_NODES * 100];          // [N][25][16] fp16 XW (80MB)

// ---------------- kernels --------------------------------------------------

__global__ void zero_deg_kernel() {
    int i = blockIdx.x * blockDim.x + threadIdx.x;
    if (i < N_NODES) g_deg[i] = 0.f;
}

__global__ void prep_kernel(const float2* __restrict__ attr,
                            const int* __restrict__ src,
                            const int* __restrict__ dst) {
    int e = blockIdx.x * blockDim.x + threadIdx.x;
    if (e >= N_EDGES) return;
    float2 a = attr[e];
    float v0 = a.x * 4.f, v1 = a.y * 4.f;
    float k0f = fminf(fmaxf(floorf(v0), 0.f), 3.f);
    float k1f = fminf(fmaxf(floorf(v1), 0.f), 3.f);
    float f0 = v0 - k0f, f1 = v1 - k1f;
    int k0 = (int)k0f, k1 = (int)k1f;
    float bj  = (1.f - f0) * (1.f - f1);
    float bj5 = (1.f - f0) * f1;
    float bj1 = f0 * (1.f - f1);
    float bj6 = f0 * f1;
    int j = k0 + 5 * k1;
    int d = dst[e];
    __half2 p0 = __floats2half2_rn(bj,  bj5);
    __half2 p1 = __floats2half2_rn(bj1, bj6);
    int4 rec;
    rec.x = src[e] | (j << 20);
    rec.y = d;
    rec.z = *reinterpret_cast<int*>(&p0);
    rec.w = *reinterpret_cast<int*>(&p1);
    g_edge[e] = rec;
    atomicAdd(&g_deg[d], 1.f);
}

__device__ __forceinline__ void red_add_v4(float* p, float4 v) {
    asm volatile("red.global.add.v4.f32 [%0], {%1,%2,%3,%4};"
                 :: "l"(p), "f"(v.x), "f"(v.y), "f"(v.z), "f"(v.w) : "memory");
}

__device__ __forceinline__ float2 h2f2(unsigned u) {
    __half2 h = *reinterpret_cast<__half2*>(&u);
    return __half22float2(h);
}

// Layer 1 edge kernel: in=2, 4 threads/edge, TWO edges per thread (MLP).
__global__ void edge1_kernel(const float2* __restrict__ x,
                             const float* __restrict__ W1) {
    __shared__ uint4 Wsh[100];                   // [25][4] fp16
    if (threadIdx.x < 100) {
        int w = threadIdx.x >> 2, l = threadIdx.x & 3;
        const float4* Wv = (const float4*)W1;    // [25][2][4] float4
        float4 a0 = Wv[w * 8 + l];
        float4 a1 = Wv[w * 8 + 4 + l];
        __half2 p0 = __floats2half2_rn(a0.x, a0.y);
        __half2 p1 = __floats2half2_rn(a0.z, a0.w);
        __half2 p2 = __floats2half2_rn(a1.x, a1.y);
        __half2 p3 = __floats2half2_rn(a1.z, a1.w);
        uint4 u;
        u.x = *reinterpret_cast<unsigned*>(&p0);
        u.y = *reinterpret_cast<unsigned*>(&p1);
        u.z = *reinterpret_cast<unsigned*>(&p2);
        u.w = *reinterpret_cast<unsigned*>(&p3);
        Wsh[w * 4 + l] = u;
    }
    __syncthreads();
    int t = blockIdx.x * blockDim.x + threadIdx.x;   // HALF_E*4 threads
    int eA = t >> 2;
    int eB = eA + HALF_E;
    int l = threadIdx.x & 3;
    // front-batch both edge records and both x gathers (MLP=4)
    int4 recA = g_edge[eA];
    int4 recB = g_edge[eB];
    int sA = recA.x & 0xFFFFF, jA = recA.x >> 20;
    int sB = recB.x & 0xFFFFF, jB = recB.x >> 20;
    float2 xvA = x[sA];
    float2 xvB = x[sB];
    const int woff[4] = {0, 5, 1, 6};
    {
        float2 b0 = h2f2(recA.z), b1 = h2f2(recA.w);
        float bs[4] = {b0.x, b0.y, b1.x, b1.y};
        float4 acc = make_float4(0.f, 0.f, 0.f, 0.f);
#pragma unroll
        for (int q = 0; q < 4; q++) {
            uint4 wv = Wsh[(jA + woff[q]) * 4 + l];
            float2 w00 = h2f2(wv.x), w01 = h2f2(wv.y);
            float2 w10 = h2f2(wv.z), w11 = h2f2(wv.w);
            float c0 = bs[q] * xvA.x, c1 = bs[q] * xvA.y;
            acc.x += c0 * w00.x + c1 * w10.x;
            acc.y += c0 * w00.y + c1 * w10.y;
            acc.z += c0 * w01.x + c1 * w11.x;
            acc.w += c0 * w01.y + c1 * w11.y;
        }
        red_add_v4((float*)&g_agg[(size_t)recA.y * 4 + l], acc);
    }
    {
        float2 b0 = h2f2(recB.z), b1 = h2f2(recB.w);
        float bs[4] = {b0.x, b0.y, b1.x, b1.y};
        float4 acc = make_float4(0.f, 0.f, 0.f, 0.f);
#pragma unroll
        for (int q = 0; q < 4; q++) {
            uint4 wv = Wsh[(jB + woff[q]) * 4 + l];
            float2 w00 = h2f2(wv.x), w01 = h2f2(wv.y);
            float2 w10 = h2f2(wv.z), w11 = h2f2(wv.w);
            float c0 = bs[q] * xvB.x, c1 = bs[q] * xvB.y;
            acc.x += c0 * w00.x + c1 * w10.x;
            acc.y += c0 * w00.y + c1 * w10.y;
            acc.z += c0 * w01.x + c1 * w11.x;
            acc.w += c0 * w01.y + c1 * w11.y;
        }
        red_add_v4((float*)&g_agg[(size_t)recB.y * 4 + l], acc);
    }
}

// XW precompute (unfused, R7 version): 128 threads, 100 active as (k,o4).
__global__ void xw_kernel(const float4* __restrict__ hin,
                          const float* __restrict__ W) {
    __shared__ float4 hs[400];                   // 100 nodes x 16 floats
    int t = threadIdx.x;
    int n0 = blockIdx.x * 100;
    int k = t >> 2, o4 = t & 3;
    float4 wc[16];
    if (t < 100) {
        const float4* Wv = (const float4*)W;     // [25][16][4]
#pragma unroll
        for (int i = 0; i < 16; i++) wc[i] = Wv[(k * 16 + i) * 4 + o4];
    }
    for (int j = t; j < 400; j += blockDim.x) hs[j] = hin[n0 * 4 + j];
    __syncthreads();
    if (t >= 100) return;
    const float* hsf = (const float*)hs;
    for (int n = 0; n < 100; n++) {
        float4 a = make_float4(0.f, 0.f, 0.f, 0.f);
#pragma unroll
        for (int i = 0; i < 16; i++) {
            float hv = hsf[n * 16 + i];
            a.x += hv * wc[i].x; a.y += hv * wc[i].y;
            a.z += hv * wc[i].z; a.w += hv * wc[i].w;
        }
        __half2 h0 = __floats2half2_rn(a.x, a.y);
        __half2 h1 = __floats2half2_rn(a.z, a.w);
        uint2 u;
        u.x = *reinterpret_cast<unsigned*>(&h0);
        u.y = *reinterpret_cast<unsigned*>(&h1);
        g_xwh[((size_t)(n0 + n) * 25 + k) * 4 + o4] = u;
    }
}

// Edge gather for layers 2/3: 4 threads/edge, TWO edges per thread (MLP=4-6).
__global__ void edge_gather_kernel() {
    int t = blockIdx.x * blockDim.x + threadIdx.x;
    int eA = t >> 2;
    int eB = eA + HALF_E;
    int l = threadIdx.x & 3;
    int4 recA = g_edge[eA];
    int4 recB = g_edge[eB];
    int sA = recA.x & 0xFFFFF, jA = recA.x >> 20;
    int sB = recB.x & 0xFFFFF, jB = recB.x >> 20;
    const char* baseA = (const char*)g_xwh + (size_t)sA * 800 + l * 16;
    const char* baseB = (const char*)g_xwh + (size_t)sB * 800 + l * 16;
    // front-batch all 4 tap-pair loads
    uint4 vA1 = *reinterpret_cast<const uint4*>(baseA + jA * 32);
    uint4 vA2 = *reinterpret_cast<const uint4*>(baseA + (jA + 5) * 32);
    uint4 vB1 = *reinterpret_cast<const uint4*>(baseB + jB * 32);
    uint4 vB2 = *reinterpret_cast<const uint4*>(baseB + (jB + 5) * 32);
    {
        float2 b0 = h2f2(recA.z), b1 = h2f2(recA.w);
        float cA = (l & 2) ? b1.x : b0.x;
        float cB = (l & 2) ? b1.y : b0.y;
        float acc[8];
        const unsigned* u1 = reinterpret_cast<const unsigned*>(&vA1);
        const unsigned* u2 = reinterpret_cast<const unsigned*>(&vA2);
#pragma unroll
        for (int i = 0; i < 4; i++) {
            float2 f1 = h2f2(u1[i]);
            float2 f2 = h2f2(u2[i]);
            acc[2 * i]     = cA * f1.x + cB * f2.x;
            acc[2 * i + 1] = cA * f1.y + cB * f2.y;
        }
#pragma unroll
        for (int i = 0; i < 8; i++)
            acc[i] += __shfl_xor_sync(FULL, acc[i], 2);
        float* ap = (float*)g_agg + (size_t)recA.y * 16 + ((l & 1) << 3) + ((l & 2) << 1);
        float4 out = (l & 2) ? make_float4(acc[4], acc[5], acc[6], acc[7])
                             : make_float4(acc[0], acc[1], acc[2], acc[3]);
        red_add_v4(ap, out);
    }
    {
        float2 b0 = h2f2(recB.z), b1 = h2f2(recB.w);
        float cA = (l & 2) ? b1.x : b0.x;
        float cB = (l & 2) ? b1.y : b0.y;
        float acc[8];
        const unsigned* u1 = reinterpret_cast<const unsigned*>(&vB1);
        const unsigned* u2 = reinterpret_cast<const unsigned*>(&vB2);
#pragma unroll
        for (int i = 0; i < 4; i++) {
            float2 f1 = h2f2(u1[i]);
            float2 f2 = h2f2(u2[i]);
            acc[2 * i]     = cA * f1.x + cB * f2.x;
            acc[2 * i + 1] = cA * f1.y + cB * f2.y;
        }
#pragma unroll
        for (int i = 0; i < 8; i++)
            acc[i] += __shfl_xor_sync(FULL, acc[i], 2);
        float* ap = (float*)g_agg + (size_t)recB.y * 16 + ((l & 1) << 3) + ((l & 2) << 1);
        float4 out = (l & 2) ? make_float4(acc[4], acc[5], acc[6], acc[7])
                             : make_float4(acc[0], acc[1], acc[2], acc[3]);
        red_add_v4(ap, out);
    }
}

// Node update, layer 1 (root: 2x16): h = relu(agg/deg + x@root + b); zero agg.
__global__ void node1_kernel(const float2* __restrict__ x,
                             const float* __restrict__ root,
                             const float* __restrict__ bias,
                             float4* __restrict__ hout) {
    __shared__ float4 rsh[8];
    __shared__ float4 bsh[4];
    if (threadIdx.x < 8)  rsh[threadIdx.x] = ((const float4*)root)[threadIdx.x];
    if (threadIdx.x < 4)  bsh[threadIdx.x] = ((const float4*)bias)[threadIdx.x];
    __syncthreads();
    int t = blockIdx.x * blockDim.x + threadIdx.x;
    int n = t >> 2;
    if (n >= N_NODES) return;
    int l = t & 3;
    float4 a = g_agg[(size_t)n * 4 + l];
    float di = 1.f / fmaxf(g_deg[n], 1.f);
    float2 xv = x[n];
    float4 r0 = rsh[l], r1 = rsh[4 + l], bb = bsh[l];
    float4 o;
    o.x = fmaxf(bb.x + a.x * di + xv.x * r0.x + xv.y * r1.x, 0.f);
    o.y = fmaxf(bb.y + a.y * di + xv.x * r0.y + xv.y * r1.y, 0.f);
    o.z = fmaxf(bb.z + a.z * di + xv.x * r0.z + xv.y * r1.z, 0.f);
    o.w = fmaxf(bb.w + a.w * di + xv.x * r0.w + xv.y * r1.w, 0.f);
    hout[(size_t)n * 4 + l] = o;
    g_agg[(size_t)n * 4 + l] = make_float4(0.f, 0.f, 0.f, 0.f);
}

// Node update, 16-channel root; 4 threads/node.
__global__ void node16_kernel(const float4* __restrict__ hin,
                              const float* __restrict__ root,
                              const float* __restrict__ bias,
                              float4* __restrict__ hout) {
    __shared__ float4 rsh[64];                   // [16][4]
    __shared__ float4 bsh[4];
    for (int j = threadIdx.x; j < 64; j += blockDim.x)
        rsh[j] = ((const float4*)root)[j];
    if (threadIdx.x < 4) bsh[threadIdx.x] = ((const float4*)bias)[threadIdx.x];
    __syncthreads();
    int t = blockIdx.x * blockDim.x + threadIdx.x;
    int n = t >> 2;
    if (n >= N_NODES) return;
    int l = t & 3;
    float4 a = g_agg[(size_t)n * 4 + l];
    float di = 1.f / fmaxf(g_deg[n], 1.f);
    float4 acc = bsh[l];
    acc.x += a.x * di; acc.y += a.y * di; acc.z += a.z * di; acc.w += a.w * di;
    const float* h = (const float*)(hin + (size_t)n * 4);
#pragma unroll
    for (int i = 0; i < 16; i++) {
        float hv = h[i];
        float4 r = rsh[i * 4 + l];
        acc.x += hv * r.x; acc.y += hv * r.y; acc.z += hv * r.z; acc.w += hv * r.w;
    }
    acc.x = fmaxf(acc.x, 0.f); acc.y = fmaxf(acc.y, 0.f);
    acc.z = fmaxf(acc.z, 0.f); acc.w = fmaxf(acc.w, 0.f);
    hout[(size_t)n * 4 + l] = acc;
    g_agg[(size_t)n * 4 + l] = make_float4(0.f, 0.f, 0.f, 0.f);
}

// Layer-3 node update fused with fc head: relu(...) -> dot fc_w -> sigmoid.
__global__ void node16_final_kernel(const float4* __restrict__ hin,
                                    const float* __restrict__ root,
                                    const float* __restrict__ bias,
                                    const float* __restrict__ fcw,
                                    const float* __restrict__ fcb,
                                    float* __restrict__ out) {
    __shared__ float4 rsh[64];
    __shared__ float4 bsh[4];
    __shared__ float4 wsh[4];
    for (int j = threadIdx.x; j < 64; j += blockDim.x)
        rsh[j] = ((const float4*)root)[j];
    if (threadIdx.x < 4) {
        bsh[threadIdx.x] = ((const float4*)bias)[threadIdx.x];
        wsh[threadIdx.x] = ((const float4*)fcw)[threadIdx.x];
    }
    __syncthreads();
    int t = blockIdx.x * blockDim.x + threadIdx.x;
    int n = t >> 2;
    if (n >= N_NODES) return;
    int l = t & 3;
    float4 a = g_agg[(size_t)n * 4 + l];
    float di = 1.f / fmaxf(g_deg[n], 1.f);
    float4 acc = bsh[l];
    acc.x += a.x * di; acc.y += a.y * di; acc.z += a.z * di; acc.w += a.w * di;
    const float* h = (const float*)(hin + (size_t)n * 4);
#pragma unroll
    for (int i = 0; i < 16; i++) {
        float hv = h[i];
        float4 r = rsh[i * 4 + l];
        acc.x += hv * r.x; acc.y += hv * r.y; acc.z += hv * r.z; acc.w += hv * r.w;
    }
    acc.x = fmaxf(acc.x, 0.f); acc.y = fmaxf(acc.y, 0.f);
    acc.z = fmaxf(acc.z, 0.f); acc.w = fmaxf(acc.w, 0.f);
    g_agg[(size_t)n * 4 + l] = make_float4(0.f, 0.f, 0.f, 0.f);
    float4 wv = wsh[l];
    float z = acc.x * wv.x + acc.y * wv.y + acc.z * wv.z + acc.w * wv.w;
    z += __shfl_xor_sync(FULL, z, 1);
    z += __shfl_xor_sync(FULL, z, 2);
    if (l == 0) out[n] = 1.f / (1.f + expf(-(z + fcb[0])));
}

// ---------------- launch ---------------------------------------------------

extern "C" void kernel_launch(void* const* d_in, const int* in_sizes, int n_in,
                              void* d_out, int out_size) {
    const float2* x     = (const float2*)d_in[0];
    const int*    ei    = (const int*)d_in[1];
    const float2* attr  = (const float2*)d_in[2];
    const float*  W1    = (const float*)d_in[3];
    const float*  root1 = (const float*)d_in[4];
    const float*  b1    = (const float*)d_in[5];
    const float*  W2    = (const float*)d_in[6];
    const float*  root2 = (const float*)d_in[7];
    const float*  b2    = (const float*)d_in[8];
    const float*  W3    = (const float*)d_in[9];
    const float*  root3 = (const float*)d_in[10];
    const float*  b3    = (const float*)d_in[11];
    const float*  fcw   = (const float*)d_in[12];
    const float*  fcb   = (const float*)d_in[13];
    const int* src = ei;
    const int* dst = ei + N_EDGES;

    float4 *h1, *h2;
    cudaGetSymbolAddress((void**)&h1, g_h1);
    cudaGetSymbolAddress((void**)&h2, g_h2);

    const int TB = 256;
    int gEdge  = (N_EDGES + TB - 1) / TB;
    int gEdge2 = (HALF_E * 4) / TB;              // 2 edges/thread: 12500
    int gNode4 = (N_NODES * 4 + TB - 1) / TB;
    int gNode  = (N_NODES + TB - 1) / TB;

    zero_deg_kernel<<<gNode, TB>>>();
    prep_kernel<<<gEdge, TB>>>(attr, src, dst);

    // layer 1 (in=2)
    edge1_kernel<<<gEdge2, TB>>>(x, W1);
    node1_kernel<<<gNode4, TB>>>(x, root1, b1, h1);

    // layer 2
    xw_kernel<<<N_NODES / 100, 128>>>(h1, W2);
    edge_gather_kernel<<<gEdge2, TB>>>();
    node16_kernel<<<gNode4, TB>>>(h1, root2, b2, h2);

    // layer 3 (node update fused with fc head)
    xw_kernel<<<N_NODES / 100, 128>>>(h2, W3);
    edge_gather_kernel<<<gEdge2, TB>>>();
    node16_final_kernel<<<gNode4, TB>>>(h2, root3, b3, fcw, fcb, (float*)d_out);
}